// round 3
// baseline (speedup 1.0000x reference)
#include <cuda_runtime.h>
#include <cstdint>

// Problem constants (fixed by the reference)
#define NUM_USERS 100000
#define NUM_ITEMS 50000
#define N_NODES   150000
#define EMB_D     64
#define NUM_EDGES 2000000

// Scratch ping-pong buffers, float4 for guaranteed 16B alignment.
#define N_ELEMS4 ((N_NODES * EMB_D) / 4)
__device__ float4 g_buf0[N_ELEMS4];
__device__ float4 g_buf1[N_ELEMS4];

// ---------------------------------------------------------------------------
// init: g_buf0 = concat(user_emb, item_emb); g_buf1 = 0; d_out = 0
// ---------------------------------------------------------------------------
__global__ void lightgcn_init_kernel(const float4* __restrict__ user4,
                                     const float4* __restrict__ item4,
                                     float4* __restrict__ out4) {
    const int total4 = N_ELEMS4;                   // 2.4M
    const int user4n = (NUM_USERS * EMB_D) / 4;    // 1.6M
    int i = blockIdx.x * blockDim.x + threadIdx.x;
    if (i >= total4) return;
    float4 v = (i < user4n) ? user4[i] : item4[i - user4n];
    g_buf0[i] = v;
    g_buf1[i] = make_float4(0.f, 0.f, 0.f, 0.f);
    out4[i]   = make_float4(0.f, 0.f, 0.f, 0.f);
}

// ---------------------------------------------------------------------------
// scatter: for each edge (r, c):
//    dst[r][:] += 0.5 * src[c][:]
//    dst[c][:] += 0.5 * src[r][:]
// One warp per edge. Lanes 0-15 handle (c -> r), lanes 16-31 handle (r -> c).
// Each half-warp covers the 64-float row as 16 x float4.
// NOTE: edge_index is int32 (JAX x64 disabled downcasts jnp.int64 -> int32).
// ---------------------------------------------------------------------------
__global__ void lightgcn_scatter_kernel(const int* __restrict__ erow,
                                        const int* __restrict__ ecol,
                                        const float4* __restrict__ src,
                                        float4* __restrict__ dst) {
    int gtid = blockIdx.x * blockDim.x + threadIdx.x;
    int edge = gtid >> 5;
    if (edge >= NUM_EDGES) return;
    int lane = gtid & 31;

    int r = erow[edge];
    int c = ecol[edge];

    int half = lane >> 4;     // 0: gather col -> scatter row; 1: reverse
    int l    = lane & 15;     // float4 slot within the 64-float row

    int sidx = half ? r : c;
    int didx = half ? c : r;

    float4 v = src[(size_t)sidx * (EMB_D / 4) + l];
    v.x *= 0.5f; v.y *= 0.5f; v.z *= 0.5f; v.w *= 0.5f;

    float4* dp = dst + (size_t)didx * (EMB_D / 4) + l;
    asm volatile("red.global.add.v4.f32 [%0], {%1, %2, %3, %4};"
                 :: "l"(dp), "f"(v.x), "f"(v.y), "f"(v.z), "f"(v.w)
                 : "memory");
}

// ---------------------------------------------------------------------------
// Launch: init -> scatter(buf0 -> buf1) -> scatter(buf1 -> out)
// ---------------------------------------------------------------------------
extern "C" void kernel_launch(void* const* d_in, const int* in_sizes, int n_in,
                              void* d_out, int out_size) {
    const int*   edge_index = (const int*)d_in[0];   // [2, E] int32
    const float* user_emb   = (const float*)d_in[1]; // [100000, 64]
    const float* item_emb   = (const float*)d_in[2]; // [50000, 64]
    float4*      out4       = (float4*)d_out;        // [150000, 64]

    const int* erow = edge_index;              // first E entries
    const int* ecol = edge_index + NUM_EDGES;  // second E entries

    float4 *buf0 = nullptr, *buf1 = nullptr;
    cudaGetSymbolAddress((void**)&buf0, g_buf0);
    cudaGetSymbolAddress((void**)&buf1, g_buf1);

    // init
    {
        int threads = 256;
        int blocks  = (N_ELEMS4 + threads - 1) / threads;
        lightgcn_init_kernel<<<blocks, threads>>>(
            (const float4*)user_emb, (const float4*)item_emb, out4);
    }

    // two propagation layers
    {
        int threads = 256;                       // 8 warps -> 8 edges / block
        long long total_threads = (long long)NUM_EDGES * 32;
        int blocks = (int)((total_threads + threads - 1) / threads);
        lightgcn_scatter_kernel<<<blocks, threads>>>(erow, ecol, buf0, buf1);
        lightgcn_scatter_kernel<<<blocks, threads>>>(erow, ecol, buf1, out4);
    }
}

// round 5
// speedup vs baseline: 2.2195x; 2.2195x over previous
#include <cuda_runtime.h>
#include <cstdint>

#define NUM_USERS 100000
#define NUM_ITEMS 50000
#define N_NODES   150000
#define EMB_D     64
#define NUM_EDGES 2000000
#define N_DIRECTED (2 * NUM_EDGES)          // 4M adjacency entries

#define N_ELEMS4 ((N_NODES * EMB_D) / 4)    // 2.4M float4
#define SCAN_TILE 1024
#define N_TILES ((N_NODES + SCAN_TILE - 1) / SCAN_TILE)  // 147

// Scratch (device globals; no allocation allowed)
__device__ float4 g_buf0[N_ELEMS4];         // concat(user, item)
__device__ float4 g_buf1[N_ELEMS4];         // layer-1 output
__device__ int    g_deg[N_NODES];
__device__ int    g_off[N_NODES];
__device__ int    g_cursor[N_NODES];
__device__ int    g_tilesum[N_TILES];
__device__ int    g_adj[N_DIRECTED];        // 16 MB

// ---------------------------------------------------------------------------
// init: buf0 = concat(user, item); deg = 0.
// ---------------------------------------------------------------------------
__global__ void init_kernel(const float4* __restrict__ user4,
                            const float4* __restrict__ item4) {
    const int user4n = (NUM_USERS * EMB_D) / 4;
    int i = blockIdx.x * blockDim.x + threadIdx.x;
    if (i < N_ELEMS4) {
        g_buf0[i] = (i < user4n) ? user4[i] : item4[i - user4n];
    }
    if (i < N_NODES) g_deg[i] = 0;
}

// degree histogram over both edge endpoints
__global__ void hist_kernel(const int* __restrict__ erow,
                            const int* __restrict__ ecol) {
    int e = blockIdx.x * blockDim.x + threadIdx.x;
    if (e >= NUM_EDGES) return;
    atomicAdd(&g_deg[erow[e]], 1);
    atomicAdd(&g_deg[ecol[e]], 1);
}

// exclusive scan, phase A: per-tile scan + tile sums
__global__ void scanA_kernel() {
    __shared__ int sh[SCAN_TILE];
    int t = threadIdx.x;
    int gid = blockIdx.x * SCAN_TILE + t;
    int v = (gid < N_NODES) ? g_deg[gid] : 0;
    sh[t] = v;
    __syncthreads();
    for (int ofs = 1; ofs < SCAN_TILE; ofs <<= 1) {
        int x = (t >= ofs) ? sh[t - ofs] : 0;
        __syncthreads();
        sh[t] += x;
        __syncthreads();
    }
    int incl = sh[t];
    if (gid < N_NODES) g_off[gid] = incl - v;          // exclusive within tile
    if (t == SCAN_TILE - 1) g_tilesum[blockIdx.x] = incl;
}

// phase B: exclusive scan of tile sums (single block; N_TILES <= 256)
__global__ void scanB_kernel() {
    __shared__ int sh[256];
    int t = threadIdx.x;
    int v = (t < N_TILES) ? g_tilesum[t] : 0;
    sh[t] = v;
    __syncthreads();
    for (int ofs = 1; ofs < 256; ofs <<= 1) {
        int x = (t >= ofs) ? sh[t - ofs] : 0;
        __syncthreads();
        sh[t] += x;
        __syncthreads();
    }
    if (t < N_TILES) g_tilesum[t] = sh[t] - v;         // exclusive
}

// phase C: add tile base, init fill cursors
__global__ void scanC_kernel() {
    int gid = blockIdx.x * blockDim.x + threadIdx.x;
    if (gid >= N_NODES) return;
    int o = g_off[gid] + g_tilesum[gid / SCAN_TILE];
    g_off[gid] = o;
    g_cursor[gid] = o;
}

// CSR fill: adjacency of both directions
__global__ void fill_kernel(const int* __restrict__ erow,
                            const int* __restrict__ ecol) {
    int e = blockIdx.x * blockDim.x + threadIdx.x;
    if (e >= NUM_EDGES) return;
    int r = erow[e], c = ecol[e];
    g_adj[atomicAdd(&g_cursor[r], 1)] = c;
    g_adj[atomicAdd(&g_cursor[c], 1)] = r;
}

// ---------------------------------------------------------------------------
// pull: dst[v] = 0.5 * sum_{u in adj(v)} src[u]
// One warp per node; each lane owns a float2 of the 64-float row.
// 8-way unrolled neighbor loop for memory-level parallelism.
// ---------------------------------------------------------------------------
__global__ void pull_kernel(const float2* __restrict__ src,
                            float2* __restrict__ dst) {
    int gwarp = (blockIdx.x * blockDim.x + threadIdx.x) >> 5;
    if (gwarp >= N_NODES) return;
    int lane = threadIdx.x & 31;
    int v = gwarp;

    int start = g_off[v];
    int d     = g_deg[v];

    float2 acc = make_float2(0.f, 0.f);
    int j = 0;
    for (; j + 8 <= d; j += 8) {
        int u0 = g_adj[start + j + 0];
        int u1 = g_adj[start + j + 1];
        int u2 = g_adj[start + j + 2];
        int u3 = g_adj[start + j + 3];
        int u4 = g_adj[start + j + 4];
        int u5 = g_adj[start + j + 5];
        int u6 = g_adj[start + j + 6];
        int u7 = g_adj[start + j + 7];
        float2 a0 = src[(size_t)u0 * 32 + lane];
        float2 a1 = src[(size_t)u1 * 32 + lane];
        float2 a2 = src[(size_t)u2 * 32 + lane];
        float2 a3 = src[(size_t)u3 * 32 + lane];
        float2 a4 = src[(size_t)u4 * 32 + lane];
        float2 a5 = src[(size_t)u5 * 32 + lane];
        float2 a6 = src[(size_t)u6 * 32 + lane];
        float2 a7 = src[(size_t)u7 * 32 + lane];
        acc.x += ((a0.x + a1.x) + (a2.x + a3.x)) + ((a4.x + a5.x) + (a6.x + a7.x));
        acc.y += ((a0.y + a1.y) + (a2.y + a3.y)) + ((a4.y + a5.y) + (a6.y + a7.y));
    }
    for (; j < d; j++) {
        int u = g_adj[start + j];
        float2 a = src[(size_t)u * 32 + lane];
        acc.x += a.x;
        acc.y += a.y;
    }
    acc.x *= 0.5f;
    acc.y *= 0.5f;
    dst[(size_t)v * 32 + lane] = acc;
}

// ---------------------------------------------------------------------------
extern "C" void kernel_launch(void* const* d_in, const int* in_sizes, int n_in,
                              void* d_out, int out_size) {
    const int*   edge_index = (const int*)d_in[0];   // [2, E] int32
    const float* user_emb   = (const float*)d_in[1];
    const float* item_emb   = (const float*)d_in[2];
    float2*      out2       = (float2*)d_out;

    const int* erow = edge_index;
    const int* ecol = edge_index + NUM_EDGES;

    float2 *buf0 = nullptr, *buf1 = nullptr;
    cudaGetSymbolAddress((void**)&buf0, g_buf0);
    cudaGetSymbolAddress((void**)&buf1, g_buf1);

    // init (copy concat + zero degrees)
    init_kernel<<<(N_ELEMS4 + 255) / 256, 256>>>(
        (const float4*)user_emb, (const float4*)item_emb);

    // CSR build
    hist_kernel<<<(NUM_EDGES + 255) / 256, 256>>>(erow, ecol);
    scanA_kernel<<<N_TILES, SCAN_TILE>>>();
    scanB_kernel<<<1, 256>>>();
    scanC_kernel<<<(N_NODES + 255) / 256, 256>>>();
    fill_kernel<<<(NUM_EDGES + 255) / 256, 256>>>(erow, ecol);

    // two pull layers (warp per node)
    {
        long long total_threads = (long long)N_NODES * 32;
        int threads = 256;
        int blocks  = (int)((total_threads + threads - 1) / threads);
        pull_kernel<<<blocks, threads>>>(buf0, buf1);
        pull_kernel<<<blocks, threads>>>(buf1, out2);
    }
}